// round 16
// baseline (speedup 1.0000x reference)
#include <cuda_runtime.h>

// Fixed problem shape
#define NMOL   256
#define NATOM  512
#define KNB    32
#define NTOT   (NMOL * NATOM)            // 131072 atoms
#define EDG    ((size_t)NTOT * KNB)      // 4194304 edges
#define TPB    128                       // 1 thread per atom
#define INFK32 0xFFFFFFFFu
#define ACCB   0x3F7FFFFFu               // (b-1) < ACCB  <=>  0 < d2 < 1
#define LOB    0x3F199999u               // (b-1) < LOB   <=>  0 < d2 < 0.6f
#define HISKIP 0x3F19999Au               // root k below this => no hi key can enter

typedef unsigned long long u64;
typedef unsigned int       u32;
typedef unsigned short     u16;

// smem: hk u32[33*TPB]=16896 + hj u16[33*TPB]=8448 + pos 6144 = 31488 B
// -> 7 blocks/SM, grid 1024 over 1036 slots: 1 wave, 1.2% imbalance.
#define HK_BYTES (33 * TPB * 4)
#define HJ_BYTES (33 * TPB * 2)
#define SMEM_BYTES (HK_BYTES + HJ_BYTES + NATOM * 12)

__device__ __forceinline__ u64 pk2(u32 lo, u32 hi) {
    u64 r; asm("mov.b64 %0, {%1, %2};" : "=l"(r) : "r"(lo), "r"(hi)); return r;
}
__device__ __forceinline__ void upk2(u64 v, u32& lo, u32& hi) {
    asm("mov.b64 {%0, %1}, %2;" : "=r"(lo), "=r"(hi) : "l"(v));
}
__device__ __forceinline__ u64 addx2(u64 a, u64 b) {
    u64 r; asm("add.rn.f32x2 %0, %1, %2;" : "=l"(r) : "l"(a), "l"(b)); return r;
}
__device__ __forceinline__ u64 mulx2(u64 a, u64 b) {
    u64 r; asm("mul.rn.f32x2 %0, %1, %2;" : "=l"(r) : "l"(a), "l"(b)); return r;
}
__device__ __forceinline__ u64 fmax2(u64 a, u64 b, u64 c) {
    u64 r; asm("fma.rn.f32x2 %0, %1, %2, %3;" : "=l"(r) : "l"(a), "l"(b), "l"(c)); return r;
}
__device__ __forceinline__ float sqrt_ap(float v) {
    float r; asm("sqrt.approx.f32 %0, %1;" : "=f"(r) : "f"(v)); return r;
}

// d2 with FMA contraction — used CONSISTENTLY in fill and stream (matches the
// packed fma.rn.f32x2 phase-1 formula bit-for-bit on the same inputs).
__device__ __forceinline__ float d2fma(float jx, float jy, float jz,
                                       float nx, float ny, float nz)
{
    const float dx = __fadd_rn(jx, nx);
    const float dy = __fadd_rn(jy, ny);
    const float dz = __fadd_rn(jz, nz);
    return __fmaf_rn(dz, dz, __fmaf_rn(dy, dy, __fmul_rn(dx, dx)));
}

// Exact lexicographic (d2bits, j) order (asc d2, then asc j).
__device__ __forceinline__ bool ltp(u32 ka, u32 ja, u32 kb, u32 jb) {
    return (ka < kb) || (ka == kb && ja < jb);
}
__device__ __forceinline__ bool gtp(u32 ka, u32 ja, u32 kb, u32 jb) {
    return (ka > kb) || (ka == kb && ja > jb);
}

// Strided heap slots (shift-add addressing, divergent-q conflict-free for HK).
#define HK(q) hk[(q) * TPB + tid]
#define HJ(q) hj[(q) * TPB + tid]

// Full-smem 4-ary sift-down (used by heapify and heapsort), size fixed at 32
// (slot 32 = pad (0,0), never wins). Depth <= 3, fully unrolled.
__device__ __forceinline__ void siftd(u32* hk, u16* hj, int tid,
                                      int p, u32 k, u32 j, u32& rk, u32& rj)
{
    if (p == 0) { rk = k; rj = j; }               // provisional root
    #pragma unroll
    for (int lvl = 0; lvl < 3; ++lvl) {
        const int l = 4 * p + 1;
        if (l > 31) break;                        // leaf
        const u32 k0 = HK(l),     j0 = HJ(l);
        const u32 k1 = HK(l + 1), j1 = HJ(l + 1);
        const u32 k2 = HK(l + 2), j2 = HJ(l + 2);
        const u32 k3 = HK(l + 3), j3 = HJ(l + 3); // p==7 -> slot 32 pad (0,0)
        u32 ak, aj, bk, bj; int ai, bi;
        if (gtp(k1, j1, k0, j0)) { ak = k1; aj = j1; ai = l + 1; }
        else                     { ak = k0; aj = j0; ai = l;     }
        if (gtp(k3, j3, k2, j2)) { bk = k3; bj = j3; bi = l + 3; }
        else                     { bk = k2; bj = j2; bi = l + 2; }
        u32 mk, mj; int mi;
        if (gtp(bk, bj, ak, aj)) { mk = bk; mj = bj; mi = bi; }
        else                     { mk = ak; mj = aj; mi = ai; }
        if (!gtp(mk, mj, k, j)) break;
        HK(p) = mk; HJ(p) = (u16)mj;
        if (p == 0) { rk = mk; rj = mj; }
        p = mi;
    }
    HK(p) = k; HJ(p) = (u16)j;
}

// Floyd heapify over all 32 slots + load level-1 children into registers.
__device__ __forceinline__ void heapify_load(u32* hk, u16* hj, int tid,
    u32& rk, u32& rj,
    u32& ck0, u32& ck1, u32& ck2, u32& ck3,
    u32& cj0, u32& cj1, u32& cj2, u32& cj3)
{
    #pragma unroll 1
    for (int p = 7; p >= 0; --p)
        siftd(hk, hj, tid, p, HK(p), HJ(p), rk, rj);
    ck0 = HK(1); cj0 = HJ(1);
    ck1 = HK(2); cj1 = HJ(2);
    ck2 = HK(3); cj2 = HJ(3);
    ck3 = HK(4); cj3 = HJ(4);
}

// Streaming sift with level-1 children in REGISTERS (level 0/1 smem-free).
// Precondition: (k,j) < (rk,rj). Levels 2..3 in smem.
__device__ __forceinline__ void sift_reg(u32* hk, u16* hj, int tid,
    u32 k, u32 j, u32& rk, u32& rj,
    u32& ck0, u32& ck1, u32& ck2, u32& ck3,
    u32& cj0, u32& cj1, u32& cj2, u32& cj3)
{
    // level 1: pure register compares
    u32 ak, aj, bk, bj; int ai, bi;
    if (gtp(ck1, cj1, ck0, cj0)) { ak = ck1; aj = cj1; ai = 1; }
    else                         { ak = ck0; aj = cj0; ai = 0; }
    if (gtp(ck3, cj3, ck2, cj2)) { bk = ck3; bj = cj3; bi = 3; }
    else                         { bk = ck2; bj = cj2; bi = 2; }
    u32 mk, mj; int mi;
    if (gtp(bk, bj, ak, aj)) { mk = bk; mj = bj; mi = bi; }
    else                     { mk = ak; mj = aj; mi = ai; }
    if (!gtp(mk, mj, k, j)) { rk = k; rj = j; return; }   // key becomes root
    rk = mk; rj = mj;                                     // promote child to root
    int p = mi + 1;                                       // heap slot of that child

    // level 2: children 4p+1..4p+4 (p in 1..4 -> slots 5..20, always exist)
    int land_l1;                                          // does key land at level 1?
    int p2;
    {
        const int l = 4 * p + 1;
        const u32 k0 = HK(l),     j0 = HJ(l);
        const u32 k1 = HK(l + 1), j1 = HJ(l + 1);
        const u32 k2 = HK(l + 2), j2 = HJ(l + 2);
        const u32 k3 = HK(l + 3), j3 = HJ(l + 3);
        u32 a2k, a2j, b2k, b2j; int a2i, b2i;
        if (gtp(k1, j1, k0, j0)) { a2k = k1; a2j = j1; a2i = l + 1; }
        else                     { a2k = k0; a2j = j0; a2i = l;     }
        if (gtp(k3, j3, k2, j2)) { b2k = k3; b2j = j3; b2i = l + 3; }
        else                     { b2k = k2; b2j = j2; b2i = l + 2; }
        u32 m2k, m2j; int m2i;
        if (gtp(b2k, b2j, a2k, a2j)) { m2k = b2k; m2j = b2j; m2i = b2i; }
        else                         { m2k = a2k; m2j = a2j; m2i = a2i; }
        land_l1 = !gtp(m2k, m2j, k, j);
        const u32 wk = land_l1 ? k : m2k;
        const u32 wj = land_l1 ? j : m2j;
        // write into reg child mi (explicit 4-way select, no local memory)
        ck0 = (mi == 0) ? wk : ck0;  cj0 = (mi == 0) ? wj : cj0;
        ck1 = (mi == 1) ? wk : ck1;  cj1 = (mi == 1) ? wj : cj1;
        ck2 = (mi == 2) ? wk : ck2;  cj2 = (mi == 2) ? wj : cj2;
        ck3 = (mi == 3) ? wk : ck3;  cj3 = (mi == 3) ? wj : cj3;
        p2 = m2i;
    }
    if (land_l1) return;
    p = p2;

    // level 3: p in 5..20; children exist iff p <= 7 (slot 32 = pad for p==7)
    {
        const int l = 4 * p + 1;
        if (l <= 31) {
            const u32 k0 = HK(l),     j0 = HJ(l);
            const u32 k1 = HK(l + 1), j1 = HJ(l + 1);
            const u32 k2 = HK(l + 2), j2 = HJ(l + 2);
            const u32 k3 = HK(l + 3), j3 = HJ(l + 3);
            u32 a3k, a3j, b3k, b3j; int a3i, b3i;
            if (gtp(k1, j1, k0, j0)) { a3k = k1; a3j = j1; a3i = l + 1; }
            else                     { a3k = k0; a3j = j0; a3i = l;     }
            if (gtp(k3, j3, k2, j2)) { b3k = k3; b3j = j3; b3i = l + 3; }
            else                     { b3k = k2; b3j = j2; b3i = l + 2; }
            u32 m3k, m3j; int m3i;
            if (gtp(b3k, b3j, a3k, a3j)) { m3k = b3k; m3j = b3j; m3i = b3i; }
            else                         { m3k = a3k; m3j = a3j; m3i = a3i; }
            if (gtp(m3k, m3j, k, j)) {
                HK(p) = m3k; HJ(p) = (u16)m3j;
                p = m3i;                          // leaf (21..31)
            }
        }
    }
    HK(p) = k; HJ(p) = (u16)j;
}

__global__ void __launch_bounds__(TPB, 7)
topo_kernel(const float* __restrict__ x, float* __restrict__ out)
{
    extern __shared__ char dsm[];
    u32*   hk = (u32*)dsm;
    u16*   hj = (u16*)(dsm + HK_BYTES);
    float* sx = (float*)(dsm + HK_BYTES + HJ_BYTES);    // 16B-aligned (8448%16==0)
    float* sy = sx + NATOM;
    float* sz = sy + NATOM;

    const int tid     = threadIdx.x;
    const int gatom   = blockIdx.x * TPB + tid;
    const int molbase = gatom & ~(NATOM - 1);
    const int i       = gatom & (NATOM - 1);

    for (int a = tid; a < NATOM; a += TPB) {
        const float* p = x + (size_t)(molbase + a) * 3;
        sx[a] = p[0]; sy[a] = p[1]; sz[a] = p[2];
    }
    __syncthreads();

    const float px = sx[i], py = sy[i], pz = sz[i];
    const float nx = -px,   ny = -py,   nz = -pz;
    const u64 npx = pk2(__float_as_uint(nx), __float_as_uint(nx));
    const u64 npy = pk2(__float_as_uint(ny), __float_as_uint(ny));
    const u64 npz = pk2(__float_as_uint(nz), __float_as_uint(nz));

    const u64* sx2 = reinterpret_cast<const u64*>(sx);
    const u64* sy2 = reinterpret_cast<const u64*>(sy);
    const u64* sz2 = reinterpret_cast<const u64*>(sz);

    // ---- Heap prefill (INFK32 = invalid; lanes with <32 neighbors keep some) ----
    #pragma unroll
    for (int q = 0; q < 32; ++q) { HK(q) = INFK32; HJ(q) = 0xFFFFu; }
    HK(32) = 0; HJ(32) = 0;                       // pad child: never promoted

    // Selection state
    u64 mhi8[8];                                  // far-accept masks (kept)
    int hc = 0;                                   // heap fill count
    int heaped = 0;
    u32 rk = INFK32, rj = 0xFFFFu;
    u32 ck0 = 0, ck1 = 0, ck2 = 0, ck3 = 0;       // level-1 children (registers)
    u32 cj0 = 0, cj1 = 0, cj2 = 0, cj3 = 0;

    // ---- Phase 1 + lo pass, per 64-atom word: compute masks with packed FMA,
    //      consume lo bits immediately (fill, then stream). lo masks are
    //      EPHEMERAL (never stored) -> 16 fewer live registers. ----
    #pragma unroll 1
    for (int w = 0; w < 8; ++w) {
        u64 ma = 0, ml = 0;
        #pragma unroll
        for (int s = 0; s < 32; ++s) {
            const int t  = w * 32 + s;
            const u64 dx = addx2(sx2[t], npx);
            const u64 dy = addx2(sy2[t], npy);
            const u64 dz = addx2(sz2[t], npz);
            const u64 d2 = fmax2(dz, dz, fmax2(dy, dy, mulx2(dx, dx)));
            u32 b0, b1; upk2(d2, b0, b1);
            if (b0 - 1u < ACCB) ma |= (1ull << (2 * s));
            if (b1 - 1u < ACCB) ma |= (2ull << (2 * s));
            if (b0 - 1u < LOB)  ml |= (1ull << (2 * s));
            if (b1 - 1u < LOB)  ml |= (2ull << (2 * s));
        }
        mhi8[w] = ma ^ ml;

        #pragma unroll 1
        while (ml) {
            const int b = __ffsll(ml) - 1;
            ml &= ml - 1;
            const int j = (w << 6) + b;
            const float d2 = d2fma(sx[j], sy[j], sz[j], nx, ny, nz);
            const u32 kb = __float_as_uint(d2);
            if (hc < 32) {
                HK(hc) = kb; HJ(hc) = (u16)j;
                ++hc;
            } else {
                if (!heaped) {
                    heapify_load(hk, hj, tid, rk, rj,
                                 ck0, ck1, ck2, ck3, cj0, cj1, cj2, cj3);
                    heaped = 1;
                }
                if (ltp(kb, (u32)j, rk, rj))
                    sift_reg(hk, hj, tid, kb, (u32)j, rk, rj,
                             ck0, ck1, ck2, ck3, cj0, cj1, cj2, cj3);
            }
        }
    }

    // ---- If not filled by lo candidates: fill from hi, then heapify. ----
    if (!heaped) {
        #pragma unroll 1
        for (int w = 0; w < 8; ++w) {
            u64 m = mhi8[w];
            #pragma unroll 1
            while (m && hc < 32) {
                const int b = __ffsll(m) - 1;
                m &= m - 1;
                const int j = (w << 6) + b;
                const float d2 = d2fma(sx[j], sy[j], sz[j], nx, ny, nz);
                HK(hc) = __float_as_uint(d2); HJ(hc) = (u16)j;
                ++hc;
            }
            mhi8[w] = m;                           // keep remaining hi bits
            if (hc == 32) break;
        }
        heapify_load(hk, hj, tid, rk, rj,
                     ck0, ck1, ck2, ck3, cj0, cj1, cj2, cj3);
        heaped = 1;
    }

    // ---- hi stream; whole pass algebraically skipped once rk < HISKIP. ----
    #pragma unroll 1
    for (int w = 0; w < 8; ++w) {
        u64 m = (rk < HISKIP) ? 0ull : mhi8[w];
        #pragma unroll 1
        while (m) {
            const int b = __ffsll(m) - 1;
            m &= m - 1;
            const int j = (w << 6) + b;
            const float d2 = d2fma(sx[j], sy[j], sz[j], nx, ny, nz);
            const u32 kb = __float_as_uint(d2);
            if (ltp(kb, (u32)j, rk, rj))
                sift_reg(hk, hj, tid, kb, (u32)j, rk, rj,
                         ck0, ck1, ck2, ck3, cj0, cj1, cj2, cj3);
        }
    }

    // ---- Write register state back to smem (root + level-1 children). ----
    HK(0) = rk;  HJ(0) = (u16)rj;
    HK(1) = ck0; HJ(1) = (u16)cj0;
    HK(2) = ck1; HJ(2) = (u16)cj1;
    HK(3) = ck2; HJ(3) = (u16)cj2;
    HK(4) = ck3; HJ(4) = (u16)cj3;

    // ---- Heapsort: 31 uniform pops, leaves slots 0..31 ascending by (k,j). ----
    #pragma unroll 1
    for (int size = 31; size >= 1; --size) {
        const u32 tk = HK(0); const u32 tj = HJ(0);
        u32 k = HK(size), j = HJ(size);
        HK(size) = tk; HJ(size) = (u16)tj;
        int p = 0;
        #pragma unroll
        for (int lvl = 0; lvl < 3; ++lvl) {
            const int l = 4 * p + 1;
            if (l >= size) break;
            const u32 k0 = HK(l),                          j0 = HJ(l);
            const u32 k1 = (l + 1 < size) ? HK(l + 1) : 0, j1 = (l + 1 < size) ? HJ(l + 1) : 0;
            const u32 k2 = (l + 2 < size) ? HK(l + 2) : 0, j2 = (l + 2 < size) ? HJ(l + 2) : 0;
            const u32 k3 = (l + 3 < size) ? HK(l + 3) : 0, j3 = (l + 3 < size) ? HJ(l + 3) : 0;
            u32 ak, aj, bk, bj; int ai, bi;
            if (gtp(k1, j1, k0, j0)) { ak = k1; aj = j1; ai = l + 1; }
            else                     { ak = k0; aj = j0; ai = l;     }
            if (gtp(k3, j3, k2, j2)) { bk = k3; bj = j3; bi = l + 3; }
            else                     { bk = k2; bj = j2; bi = l + 2; }
            u32 mk, mj; int mi;
            if (gtp(bk, bj, ak, aj)) { mk = bk; mj = bj; mi = bi; }
            else                     { mk = ak; mj = aj; mi = ai; }
            if (!gtp(mk, mj, k, j)) break;
            HK(p) = mk; HJ(p) = (u16)mj;
            p = mi;
        }
        HK(p) = k; HJ(p) = (u16)j;
    }

    // ---- Emit, per-atom contiguous -> all float4 stores. ----
    float* obi  = out + (size_t)gatom * KNB;
    float* obj  = out + EDG + (size_t)gatom * KNB;
    float* ovec = out + 2 * EDG + (size_t)gatom * (3 * KNB);
    float* odst = out + 5 * EDG + (size_t)gatom * KNB;
    float* oval = out + 6 * EDG + (size_t)gatom * KNB;

    const float fgi = (float)gatom;

    #pragma unroll
    for (int qb = 0; qb < KNB / 4; ++qb) {
        float bi4[4], bj4[4], dd4[4], vv4[4], vec12[12];
        #pragma unroll
        for (int u = 0; u < 4; ++u) {
            const int  s   = qb * 4 + u;
            const u32  d2b = HK(s);
            const bool ok  = (d2b != INFK32);     // real keys <= 0x3F7FFFFF
            const int  j   = (int)HJ(s) & (NATOM - 1);
            const float dx = __fadd_rn(sx[j], nx);
            const float dy = __fadd_rn(sy[j], ny);
            const float dz = __fadd_rn(sz[j], nz);
            vec12[u * 3 + 0] = ok ? dx : 0.0f;
            vec12[u * 3 + 1] = ok ? dy : 0.0f;
            vec12[u * 3 + 2] = ok ? dz : 0.0f;
            bi4[u] = ok ? fgi : -1.0f;
            bj4[u] = ok ? (float)(molbase + j) : -1.0f;
            dd4[u] = ok ? sqrt_ap(__uint_as_float(d2b)) : 0.0f;
            vv4[u] = ok ? 1.0f : 0.0f;
        }
        *(float4*)(obi  + qb * 4)      = make_float4(bi4[0], bi4[1], bi4[2], bi4[3]);
        *(float4*)(obj  + qb * 4)      = make_float4(bj4[0], bj4[1], bj4[2], bj4[3]);
        *(float4*)(odst + qb * 4)      = make_float4(dd4[0], dd4[1], dd4[2], dd4[3]);
        *(float4*)(oval + qb * 4)      = make_float4(vv4[0], vv4[1], vv4[2], vv4[3]);
        *(float4*)(ovec + qb * 12 + 0) = make_float4(vec12[0], vec12[1], vec12[2],  vec12[3]);
        *(float4*)(ovec + qb * 12 + 4) = make_float4(vec12[4], vec12[5], vec12[6],  vec12[7]);
        *(float4*)(ovec + qb * 12 + 8) = make_float4(vec12[8], vec12[9], vec12[10], vec12[11]);
    }
}

extern "C" void kernel_launch(void* const* d_in, const int* in_sizes, int n_in,
                              void* d_out, int out_size)
{
    const float* x   = (const float*)d_in[0];
    float*       out = (float*)d_out;

    cudaFuncSetAttribute(topo_kernel, cudaFuncAttributeMaxDynamicSharedMemorySize,
                         SMEM_BYTES);
    topo_kernel<<<NTOT / TPB, TPB, SMEM_BYTES>>>(x, out);
}

// round 17
// speedup vs baseline: 1.2132x; 1.2132x over previous
#include <cuda_runtime.h>

// Fixed problem shape
#define NMOL   256
#define NATOM  512
#define KNB    32
#define NTOT   (NMOL * NATOM)            // 131072 atoms
#define EDG    ((size_t)NTOT * KNB)      // 4194304 edges
#define TPB    128                       // 1 thread per atom
#define INFK32 0xFFFFFFFFu
#define ACCB   0x3F7FFFFFu               // (b-1) < ACCB  <=>  0 < d2 < 1
#define LOB    0x3F199999u               // (b-1) < LOB   <=>  0 < d2 < 0.6f
#define HISKIP 0x3F19999Au               // root k below this => no hi key can enter

typedef unsigned long long u64;
typedef unsigned int       u32;
typedef unsigned short     u16;

// smem: hk u32[33*TPB]=16896 + hj u16[33*TPB]=8448 + pos 6144 = 31488 B
// -> 7 blocks/SM, grid 1024 over 1036 slots: 1 wave, 1.2% imbalance.
#define HK_BYTES (33 * TPB * 4)
#define HJ_BYTES (33 * TPB * 2)
#define SMEM_BYTES (HK_BYTES + HJ_BYTES + NATOM * 12)

__device__ __forceinline__ u64 pk2(u32 lo, u32 hi) {
    u64 r; asm("mov.b64 %0, {%1, %2};" : "=l"(r) : "r"(lo), "r"(hi)); return r;
}
__device__ __forceinline__ void upk2(u64 v, u32& lo, u32& hi) {
    asm("mov.b64 {%0, %1}, %2;" : "=r"(lo), "=r"(hi) : "l"(v));
}
__device__ __forceinline__ u64 addx2(u64 a, u64 b) {
    u64 r; asm("add.rn.f32x2 %0, %1, %2;" : "=l"(r) : "l"(a), "l"(b)); return r;
}
__device__ __forceinline__ u64 mulx2(u64 a, u64 b) {
    u64 r; asm("mul.rn.f32x2 %0, %1, %2;" : "=l"(r) : "l"(a), "l"(b)); return r;
}
__device__ __forceinline__ u64 fmax2(u64 a, u64 b, u64 c) {
    u64 r; asm("fma.rn.f32x2 %0, %1, %2, %3;" : "=l"(r) : "l"(a), "l"(b), "l"(c)); return r;
}
__device__ __forceinline__ float sqrt_ap(float v) {
    float r; asm("sqrt.approx.f32 %0, %1;" : "=f"(r) : "f"(v)); return r;
}

// d2 with FMA contraction — used CONSISTENTLY in fill and stream (matches the
// packed fma.rn.f32x2 phase-1 formula bit-for-bit on the same inputs).
__device__ __forceinline__ float d2fma(float jx, float jy, float jz,
                                       float nx, float ny, float nz)
{
    const float dx = __fadd_rn(jx, nx);
    const float dy = __fadd_rn(jy, ny);
    const float dz = __fadd_rn(jz, nz);
    return __fmaf_rn(dz, dz, __fmaf_rn(dy, dy, __fmul_rn(dx, dx)));
}

// Exact lexicographic (d2bits, j) order (asc d2, then asc j).
__device__ __forceinline__ bool ltp(u32 ka, u32 ja, u32 kb, u32 jb) {
    return (ka < kb) || (ka == kb && ja < jb);
}
__device__ __forceinline__ bool gtp(u32 ka, u32 ja, u32 kb, u32 jb) {
    return (ka > kb) || (ka == kb && ja > jb);
}

// Strided heap slots (shift-add addressing, divergent-q conflict-free for HK).
#define HK(q) hk[(q) * TPB + tid]
#define HJ(q) hj[(q) * TPB + tid]

// 4-ary max-heap sift-down, fixed size 32 (slot 32 = pad (0,0), never wins).
// Depth <= 3: fully unrolled. Updates (rk, rj) when the root slot changes.
__device__ __forceinline__ void siftd(u32* hk, u16* hj, int tid,
                                      int p, u32 k, u32 j, u32& rk, u32& rj)
{
    if (p == 0) { rk = k; rj = j; }               // provisional root
    #pragma unroll
    for (int lvl = 0; lvl < 3; ++lvl) {
        const int l = 4 * p + 1;
        if (l > 31) break;                        // leaf
        const u32 k0 = HK(l),     j0 = HJ(l);
        const u32 k1 = HK(l + 1), j1 = HJ(l + 1);
        const u32 k2 = HK(l + 2), j2 = HJ(l + 2);
        const u32 k3 = HK(l + 3), j3 = HJ(l + 3); // p==7 -> slot 32 pad (0,0)
        u32 ak, aj, bk, bj; int ai, bi;
        if (gtp(k1, j1, k0, j0)) { ak = k1; aj = j1; ai = l + 1; }
        else                     { ak = k0; aj = j0; ai = l;     }
        if (gtp(k3, j3, k2, j2)) { bk = k3; bj = j3; bi = l + 3; }
        else                     { bk = k2; bj = j2; bi = l + 2; }
        u32 mk, mj; int mi;
        if (gtp(bk, bj, ak, aj)) { mk = bk; mj = bj; mi = bi; }
        else                     { mk = ak; mj = aj; mi = ai; }
        if (!gtp(mk, mj, k, j)) break;
        HK(p) = mk; HJ(p) = (u16)mj;
        if (p == 0) { rk = mk; rj = mj; }
        p = mi;
    }
    HK(p) = k; HJ(p) = (u16)j;
}

// Stream one u64 mask word through the full heap (replace-root when better).
__device__ __forceinline__ void stream_word(
    u32* hk, u16* hj, int tid, u64 m, int w,
    const float* sx, const float* sy, const float* sz,
    float nx, float ny, float nz, u32& rk, u32& rj)
{
    #pragma unroll 1
    while (m) {
        const int b = __ffsll(m) - 1;
        m &= m - 1;
        const int j = (w << 6) + b;
        const float d2 = d2fma(sx[j], sy[j], sz[j], nx, ny, nz);
        const u32 kb = __float_as_uint(d2);
        if (ltp(kb, (u32)j, rk, rj))
            siftd(hk, hj, tid, 0, kb, (u32)j, rk, rj);
    }
}

__global__ void __launch_bounds__(TPB, 7)
topo_kernel(const float* __restrict__ x, float* __restrict__ out)
{
    extern __shared__ char dsm[];
    u32*   hk = (u32*)dsm;
    u16*   hj = (u16*)(dsm + HK_BYTES);
    float* sx = (float*)(dsm + HK_BYTES + HJ_BYTES);    // 16B-aligned (25344%16==0)
    float* sy = sx + NATOM;                              // +2048B, 16B-aligned
    float* sz = sy + NATOM;

    const int tid     = threadIdx.x;
    const int gatom   = blockIdx.x * TPB + tid;
    const int molbase = gatom & ~(NATOM - 1);
    const int i       = gatom & (NATOM - 1);

    for (int a = tid; a < NATOM; a += TPB) {
        const float* p = x + (size_t)(molbase + a) * 3;
        sx[a] = p[0]; sy[a] = p[1]; sz[a] = p[2];
    }
    __syncthreads();

    const float px = sx[i], py = sy[i], pz = sz[i];
    const float nx = -px,   ny = -py,   nz = -pz;
    const u64 npx = pk2(__float_as_uint(nx), __float_as_uint(nx));
    const u64 npy = pk2(__float_as_uint(ny), __float_as_uint(ny));
    const u64 npz = pk2(__float_as_uint(nz), __float_as_uint(nz));

    // LDS.128 views: one load = 4 atoms' coords (2 packed f32x2 pairs).
    const ulonglong2* sx4 = reinterpret_cast<const ulonglong2*>(sx);
    const ulonglong2* sy4 = reinterpret_cast<const ulonglong2*>(sy);
    const ulonglong2* sz4 = reinterpret_cast<const ulonglong2*>(sz);

    // ---- Phase 1: distances 4-at-a-time (3x LDS.128 + packed FMA; values and
    //      FP ops bit-identical to the 2-at-a-time version). u64 masks:
    //      mlo = near (0<d2<0.6), mhi = far (0.6<=d2<1). ----
    u64 mlo8[8], mhi8[8];

    #pragma unroll 1
    for (int w = 0; w < 8; ++w) {
        u64 ma = 0, ml = 0;
        #pragma unroll
        for (int s = 0; s < 16; ++s) {
            const int t = w * 16 + s;
            const ulonglong2 X = sx4[t];
            const ulonglong2 Y = sy4[t];
            const ulonglong2 Z = sz4[t];
            const u64 dxa = addx2(X.x, npx), dxb = addx2(X.y, npx);
            const u64 dya = addx2(Y.x, npy), dyb = addx2(Y.y, npy);
            const u64 dza = addx2(Z.x, npz), dzb = addx2(Z.y, npz);
            const u64 d2a = fmax2(dza, dza, fmax2(dya, dya, mulx2(dxa, dxa)));
            const u64 d2b = fmax2(dzb, dzb, fmax2(dyb, dyb, mulx2(dxb, dxb)));
            u32 b0, b1, b2, b3;
            upk2(d2a, b0, b1);
            upk2(d2b, b2, b3);
            if (b0 - 1u < ACCB) ma |= (1ull << (4 * s));
            if (b1 - 1u < ACCB) ma |= (2ull << (4 * s));
            if (b2 - 1u < ACCB) ma |= (4ull << (4 * s));
            if (b3 - 1u < ACCB) ma |= (8ull << (4 * s));
            if (b0 - 1u < LOB)  ml |= (1ull << (4 * s));
            if (b1 - 1u < LOB)  ml |= (2ull << (4 * s));
            if (b2 - 1u < LOB)  ml |= (4ull << (4 * s));
            if (b3 - 1u < LOB)  ml |= (8ull << (4 * s));
        }
        mhi8[w] = ma ^ ml;
        mlo8[w] = ml;
    }

    // ---- Heap prefill (INFK32 = invalid; lanes with <32 neighbors keep some) ----
    #pragma unroll
    for (int q = 0; q < 32; ++q) { HK(q) = INFK32; HJ(q) = 0xFFFFu; }
    HK(32) = 0; HJ(32) = 0;                       // pad child: never promoted

    // ---- Stage A: append-only fill, near candidates first, then far. ----
    int hc = 0;
    int wr = 8; u64 mr = 0;                       // lo resume point
    int wh = 8; u64 mh = 0;                       // hi resume point

    #pragma unroll 1
    for (int w = 0; w < 8; ++w) {
        u64 m = mlo8[w];
        #pragma unroll 1
        while (m && hc < 32) {
            const int b = __ffsll(m) - 1;
            m &= m - 1;
            const int j = (w << 6) + b;
            const float d2 = d2fma(sx[j], sy[j], sz[j], nx, ny, nz);
            HK(hc) = __float_as_uint(d2); HJ(hc) = (u16)j;
            ++hc;
        }
        if (m) { wr = w; mr = m; break; }         // heap filled, lo bits remain
    }

    if (hc == 32) {
        wh = 0; mh = mhi8[0];                     // entire hi pass pending
    } else {
        #pragma unroll 1
        for (int w = 0; w < 8; ++w) {
            u64 m = mhi8[w];
            #pragma unroll 1
            while (m && hc < 32) {
                const int b = __ffsll(m) - 1;
                m &= m - 1;
                const int j = (w << 6) + b;
                const float d2 = d2fma(sx[j], sy[j], sz[j], nx, ny, nz);
                HK(hc) = __float_as_uint(d2); HJ(hc) = (u16)j;
                ++hc;
            }
            if (m) { wh = w; mh = m; break; }
        }
    }

    // ---- Floyd heapify: uniform 8 sift-downs (4-ary, depth <= 3) ----
    u32 rk = INFK32, rj = 0xFFFFu;
    #pragma unroll 1
    for (int p = 7; p >= 0; --p)
        siftd(hk, hj, tid, p, HK(p), HJ(p), rk, rj);  // p==0 call yields true root

    // ---- Stage B: stream remainders. Near first; far pass skipped
    //      algebraically once rk < 0x3F19999A (no far key can beat root). ----
    if (wr < 8) {
        stream_word(hk, hj, tid, mr, wr, sx, sy, sz, nx, ny, nz, rk, rj);
        #pragma unroll 1
        for (int w = wr + 1; w < 8; ++w)
            stream_word(hk, hj, tid, mlo8[w], w, sx, sy, sz, nx, ny, nz, rk, rj);
    }
    if (wh < 8) {
        u64 m0 = (rk < HISKIP) ? 0ull : mh;
        stream_word(hk, hj, tid, m0, wh, sx, sy, sz, nx, ny, nz, rk, rj);
        #pragma unroll 1
        for (int w = wh + 1; w < 8; ++w) {
            u64 m = (rk < HISKIP) ? 0ull : mhi8[w];
            stream_word(hk, hj, tid, m, w, sx, sy, sz, nx, ny, nz, rk, rj);
        }
    }

    // ---- Heapsort: 31 uniform pops (INFK32s land in the tail slots),
    //      leaves slots 0..31 ascending by (d2bits, j). ----
    #pragma unroll 1
    for (int size = 31; size >= 1; --size) {
        const u32 tk = HK(0); const u32 tj = HJ(0);
        u32 k = HK(size), j = HJ(size);
        HK(size) = tk; HJ(size) = (u16)tj;
        int p = 0;
        #pragma unroll
        for (int lvl = 0; lvl < 3; ++lvl) {
            const int l = 4 * p + 1;
            if (l >= size) break;
            const u32 k0 = HK(l),                          j0 = HJ(l);
            const u32 k1 = (l + 1 < size) ? HK(l + 1) : 0, j1 = (l + 1 < size) ? HJ(l + 1) : 0;
            const u32 k2 = (l + 2 < size) ? HK(l + 2) : 0, j2 = (l + 2 < size) ? HJ(l + 2) : 0;
            const u32 k3 = (l + 3 < size) ? HK(l + 3) : 0, j3 = (l + 3 < size) ? HJ(l + 3) : 0;
            u32 ak, aj, bk, bj; int ai, bi;
            if (gtp(k1, j1, k0, j0)) { ak = k1; aj = j1; ai = l + 1; }
            else                     { ak = k0; aj = j0; ai = l;     }
            if (gtp(k3, j3, k2, j2)) { bk = k3; bj = j3; bi = l + 3; }
            else                     { bk = k2; bj = j2; bi = l + 2; }
            u32 mk, mj; int mi;
            if (gtp(bk, bj, ak, aj)) { mk = bk; mj = bj; mi = bi; }
            else                     { mk = ak; mj = aj; mi = ai; }
            if (!gtp(mk, mj, k, j)) break;
            HK(p) = mk; HJ(p) = (u16)mj;
            p = mi;
        }
        HK(p) = k; HJ(p) = (u16)j;
    }

    // ---- Phase 3: emit, per-atom contiguous -> all float4 stores. ----
    float* obi  = out + (size_t)gatom * KNB;
    float* obj  = out + EDG + (size_t)gatom * KNB;
    float* ovec = out + 2 * EDG + (size_t)gatom * (3 * KNB);
    float* odst = out + 5 * EDG + (size_t)gatom * KNB;
    float* oval = out + 6 * EDG + (size_t)gatom * KNB;

    const float fgi = (float)gatom;

    #pragma unroll
    for (int qb = 0; qb < KNB / 4; ++qb) {
        float bi4[4], bj4[4], dd4[4], vv4[4], vec12[12];
        #pragma unroll
        for (int u = 0; u < 4; ++u) {
            const int  s   = qb * 4 + u;
            const u32  d2b = HK(s);
            const bool ok  = (d2b != INFK32);     // real keys <= 0x3F7FFFFF
            const int  j   = (int)HJ(s) & (NATOM - 1);
            const float dx = __fadd_rn(sx[j], nx);
            const float dy = __fadd_rn(sy[j], ny);
            const float dz = __fadd_rn(sz[j], nz);
            vec12[u * 3 + 0] = ok ? dx : 0.0f;
            vec12[u * 3 + 1] = ok ? dy : 0.0f;
            vec12[u * 3 + 2] = ok ? dz : 0.0f;
            bi4[u] = ok ? fgi : -1.0f;
            bj4[u] = ok ? (float)(molbase + j) : -1.0f;
            dd4[u] = ok ? sqrt_ap(__uint_as_float(d2b)) : 0.0f;
            vv4[u] = ok ? 1.0f : 0.0f;
        }
        *(float4*)(obi  + qb * 4)      = make_float4(bi4[0], bi4[1], bi4[2], bi4[3]);
        *(float4*)(obj  + qb * 4)      = make_float4(bj4[0], bj4[1], bj4[2], bj4[3]);
        *(float4*)(odst + qb * 4)      = make_float4(dd4[0], dd4[1], dd4[2], dd4[3]);
        *(float4*)(oval + qb * 4)      = make_float4(vv4[0], vv4[1], vv4[2], vv4[3]);
        *(float4*)(ovec + qb * 12 + 0) = make_float4(vec12[0], vec12[1], vec12[2],  vec12[3]);
        *(float4*)(ovec + qb * 12 + 4) = make_float4(vec12[4], vec12[5], vec12[6],  vec12[7]);
        *(float4*)(ovec + qb * 12 + 8) = make_float4(vec12[8], vec12[9], vec12[10], vec12[11]);
    }
}

extern "C" void kernel_launch(void* const* d_in, const int* in_sizes, int n_in,
                              void* d_out, int out_size)
{
    const float* x   = (const float*)d_in[0];
    float*       out = (float*)d_out;

    cudaFuncSetAttribute(topo_kernel, cudaFuncAttributeMaxDynamicSharedMemorySize,
                         SMEM_BYTES);
    topo_kernel<<<NTOT / TPB, TPB, SMEM_BYTES>>>(x, out);
}